// round 4
// baseline (speedup 1.0000x reference)
#include <cuda_runtime.h>
#include <cstring>

#define VOCAB 512
#define EMBD  128
#define HID   64
#define BATCH 256
#define TLEN  1024

// Precomputed layer-0 input table: P0[v][j] = bih0[j] + bhh0[j] + emb[v] . Wih0[j]
__device__ float g_P0[VOCAB * HID];

// ---------------------------------------------------------------------------
// Kernel 1: precompute P0 (512 x 64, each a 128-dot). Trivial cost.
// ---------------------------------------------------------------------------
__global__ void precompute_P0(const float* __restrict__ emb,
                              const float* __restrict__ Wih0,
                              const float* __restrict__ bih0,
                              const float* __restrict__ bhh0)
{
    __shared__ float embs[EMBD];
    __shared__ float ws[HID * (EMBD + 1)];
    const int v = blockIdx.x;
    const int j = threadIdx.x;               // 64 threads

    embs[j]      = emb[v * EMBD + j];
    embs[j + 64] = emb[v * EMBD + j + 64];
    for (int r = 0; r < HID; r++) {
        ws[r * (EMBD + 1) + j]      = Wih0[r * EMBD + j];
        ws[r * (EMBD + 1) + j + 64] = Wih0[r * EMBD + j + 64];
    }
    __syncthreads();

    float acc = bih0[j] + bhh0[j];
    #pragma unroll
    for (int k = 0; k < EMBD; k++)
        acc += embs[k] * ws[j * (EMBD + 1) + k];
    g_P0[v * HID + j] = acc;
}

// ---------------------------------------------------------------------------
// Packed-f32x2 FMA (Blackwell FFMA2 — only reachable via PTX fma.rn.f32x2)
// ---------------------------------------------------------------------------
__device__ __forceinline__ void ffma2(unsigned long long& d,
                                      unsigned long long a,
                                      unsigned long long b)
{
    asm("fma.rn.f32x2 %0, %1, %2, %0;" : "+l"(d) : "l"(a), "l"(b));
}

__device__ __forceinline__ float hsum2(unsigned long long a)
{
    float2 f;
    memcpy(&f, &a, 8);
    return f.x + f.y;
}

__device__ __forceinline__ float tanh_fast(float x)
{
    float y;
    asm("tanh.approx.f32 %0, %1;" : "=f"(y) : "f"(x));
    return y;
}

// ---------------------------------------------------------------------------
// Kernel 2: fused 2-layer RNN scan + head.
//
// Grid: 128 CTAs x 256 threads. CTA owns 2 batches; each batch group has
// 128 threads (4 warps). Group g = tid>>7 uses warps {4g..4g+3}, so every
// SMSP holds one warp from EACH group -> independent barriers interleave,
// hiding the serial recurrence tail of one group under the FFMA issue of
// the other.
//
// Thread r (in group): u = r>>1 (hidden unit), kh = r&1 (k-half).
//   r0 partial: Whh0[u][kh-half] . h0_old          (32 MAC)
//   q  partial: Wih1[u][kh-half] . h0_old
//             + Whh1[u][kh-half] . h1_old           (64 MAC)
// Halves combine with ONE in-warp shfl_xor(1) (lanes 2u,2u+1 adjacent).
// kh=0 finalizes h0[u] = tanh(r0_full + P0[tok][u]);
// kh=1 finalizes h1[u] = tanh(q_full + c1).
// One 128-thread named barrier per phase. Layers software-pipelined:
// phase p produces h0[p] and h1[p-1].
// ---------------------------------------------------------------------------
__global__ __launch_bounds__(256, 1)
void rnn_scan_kernel(const int*   __restrict__ x,
                     const float* __restrict__ Whh0,
                     const float* __restrict__ Wih1,
                     const float* __restrict__ Whh1,
                     const float* __restrict__ bih1,
                     const float* __restrict__ bhh1,
                     const float* __restrict__ W1,
                     const float* __restrict__ b1,
                     const float* __restrict__ W2,
                     const float* __restrict__ b2,
                     float*       __restrict__ out)
{
    extern __shared__ float smem[];
    // layout: P0s[VOCAB*HID] | xs[2*TLEN] (int) | hbuf[512]
    float* P0s  = smem;
    int*   xs   = (int*)(smem + VOCAB * HID);
    float* hbuf = smem + VOCAB * HID + 2 * TLEN;

    const int tid  = threadIdx.x;
    const int g    = tid >> 7;       // batch group within CTA
    const int r    = tid & 127;
    const int u    = r >> 1;         // hidden unit
    const int kh   = r & 1;          // k-half
    const int bidx = blockIdx.x * 2 + g;

    // ---- stage P0 table (float4), token rows; zero h buffers
    {
        const float4* srcp = (const float4*)g_P0;
        float4*       dstp = (float4*)P0s;
        for (int i = tid; i < (VOCAB * HID) / 4; i += 256) dstp[i] = srcp[i];
    }
    for (int i = tid; i < 2 * TLEN; i += 256)
        xs[i] = x[(blockIdx.x * 2 + (i >> 10)) * TLEN + (i & (TLEN - 1))];
    for (int i = tid; i < 512; i += 256) hbuf[i] = 0.0f;

    // ---- pack this thread's k-half weights into f32x2 registers (48 u64)
    unsigned long long w0p[16], w1p[16], w2p[16];
    {
        const unsigned long long* a  = (const unsigned long long*)(Whh0 + u * HID + kh * 32);
        const unsigned long long* bq = (const unsigned long long*)(Wih1 + u * HID + kh * 32);
        const unsigned long long* c  = (const unsigned long long*)(Whh1 + u * HID + kh * 32);
        #pragma unroll
        for (int k = 0; k < 16; k++) { w0p[k] = a[k]; w1p[k] = bq[k]; w2p[k] = c[k]; }
    }
    const float c1 = bih1[u] + bhh1[u];

    __syncthreads();

    float* base = hbuf + g * 256;
    float* h0b0 = base;        // h0 buffer 0
    float* h0b1 = base + 64;   // h0 buffer 1
    float* h1b0 = base + 128;  // h1 buffer 0
    float* h1b1 = base + 192;  // h1 buffer 1
    const int barid = 1 + g;

    for (int p = 0; p <= TLEN; p++) {
        const int rb = p & 1;
        // each thread reads only its 32-float k-half (8 x 16B)
        const ulonglong2* h0old =
            (const ulonglong2*)((rb ? h0b1 : h0b0) + kh * 32);
        const ulonglong2* h1old =
            (const ulonglong2*)((rb ? h1b1 : h1b0) + kh * 32);
        float* h0w = rb ? h0b0 : h0b1;
        float* h1w = rb ? h1b0 : h1b1;

        // token / P0 lookup early (dependent LDS->LDS chain, hidden under FFMAs)
        const int   tt  = (p < TLEN) ? p : (TLEN - 1);
        const int   tok = xs[g * TLEN + tt];
        const float p0v = P0s[tok * HID + u];

        // ---- L0 partial + L1a partial over h0_old (one pass of loads)
        unsigned long long a0 = 0, a1 = 0, b0a = 0, b1a = 0;
        #pragma unroll
        for (int jj = 0; jj < 8; jj++) {
            ulonglong2 hv = h0old[jj];
            ffma2(a0,  hv.x, w0p[2 * jj]);
            ffma2(a1,  hv.y, w0p[2 * jj + 1]);
            ffma2(b0a, hv.x, w1p[2 * jj]);
            ffma2(b1a, hv.y, w1p[2 * jj + 1]);
        }
        // finish the h0 recurrence path as early as possible
        float r0 = hsum2(a0) + hsum2(a1);
        r0 += __shfl_xor_sync(0xffffffffu, r0, 1);
        if (kh == 0)
            h0w[u] = tanh_fast(r0 + p0v);

        // ---- L1b partial over h1_old
        unsigned long long c0 = 0, c1a = 0;
        #pragma unroll
        for (int jj = 0; jj < 8; jj++) {
            ulonglong2 gv = h1old[jj];
            ffma2(c0,  gv.x, w2p[2 * jj]);
            ffma2(c1a, gv.y, w2p[2 * jj + 1]);
        }
        float q = (hsum2(b0a) + hsum2(b1a)) + (hsum2(c0) + hsum2(c1a));
        q += __shfl_xor_sync(0xffffffffu, q, 1);
        if (kh == 1)
            h1w[u] = (p == 0) ? 0.0f : tanh_fast(q + c1);

        asm volatile("bar.sync %0, 128;" :: "r"(barid) : "memory");
    }

    // phase p=TLEN (rb=0) wrote h1[T-1] into h1b1
    const float* h1f = h1b1;

    // ---- head: y = relu(h1f @ W1^T + b1) @ W2^T + b2  (first warp of group)
    if (r < 32) {
        float acc = b1[r];
        #pragma unroll
        for (int k = 0; k < HID; k++)
            acc += W1[r * HID + k] * h1f[k];
        acc = fmaxf(acc, 0.0f);
        float s = acc * W2[r];
        #pragma unroll
        for (int off = 16; off; off >>= 1)
            s += __shfl_down_sync(0xffffffffu, s, off);
        if (r == 0) out[bidx] = s + b2[0];
    }
}

// ---------------------------------------------------------------------------
extern "C" void kernel_launch(void* const* d_in, const int* in_sizes, int n_in,
                              void* d_out, int out_size)
{
    const int*   x    = (const int*)  d_in[0];
    const float* emb  = (const float*)d_in[1];
    const float* Wih0 = (const float*)d_in[2];
    const float* Whh0 = (const float*)d_in[3];
    const float* bih0 = (const float*)d_in[4];
    const float* bhh0 = (const float*)d_in[5];
    const float* Wih1 = (const float*)d_in[6];
    const float* Whh1 = (const float*)d_in[7];
    const float* bih1 = (const float*)d_in[8];
    const float* bhh1 = (const float*)d_in[9];
    const float* W1   = (const float*)d_in[10];
    const float* b1   = (const float*)d_in[11];
    const float* W2   = (const float*)d_in[12];
    const float* b2   = (const float*)d_in[13];
    float* out = (float*)d_out;

    precompute_P0<<<VOCAB, 64>>>(emb, Wih0, bih0, bhh0);

    const int smem_bytes = (VOCAB * HID + 2 * TLEN + 512) * 4;  // 141,312 B
    cudaFuncSetAttribute(rnn_scan_kernel,
                         cudaFuncAttributeMaxDynamicSharedMemorySize, smem_bytes);
    rnn_scan_kernel<<<BATCH / 2, 256, smem_bytes>>>(
        x, Whh0, Wih1, Whh1, bih1, bhh1, W1, b1, W2, b2, out);
}

// round 5
// speedup vs baseline: 1.3877x; 1.3877x over previous
#include <cuda_runtime.h>
#include <cstring>

#define VOCAB 512
#define EMBD  128
#define HID   64
#define BATCH 256
#define TLEN  1024

// Precomputed layer-0 input table: P0[v][j] = bih0[j] + bhh0[j] + emb[v] . Wih0[j]
__device__ float g_P0[VOCAB * HID];

// ---------------------------------------------------------------------------
// Kernel 1: precompute P0 (512 x 64, each a 128-dot). Trivial cost.
// ---------------------------------------------------------------------------
__global__ void precompute_P0(const float* __restrict__ emb,
                              const float* __restrict__ Wih0,
                              const float* __restrict__ bih0,
                              const float* __restrict__ bhh0)
{
    __shared__ float embs[EMBD];
    __shared__ float ws[HID * (EMBD + 1)];
    const int v = blockIdx.x;
    const int j = threadIdx.x;               // 64 threads

    embs[j]      = emb[v * EMBD + j];
    embs[j + 64] = emb[v * EMBD + j + 64];
    for (int r = 0; r < HID; r++) {
        ws[r * (EMBD + 1) + j]      = Wih0[r * EMBD + j];
        ws[r * (EMBD + 1) + j + 64] = Wih0[r * EMBD + j + 64];
    }
    __syncthreads();

    float acc = bih0[j] + bhh0[j];
    #pragma unroll
    for (int k = 0; k < EMBD; k++)
        acc += embs[k] * ws[j * (EMBD + 1) + k];
    g_P0[v * HID + j] = acc;
}

// ---------------------------------------------------------------------------
// Packed f32x2 helpers (Blackwell FFMA2 / FADD2 — PTX-only)
// ---------------------------------------------------------------------------
__device__ __forceinline__ void ffma2(unsigned long long& d,
                                      unsigned long long a,
                                      unsigned long long b)
{
    asm("fma.rn.f32x2 %0, %1, %2, %0;" : "+l"(d) : "l"(a), "l"(b));
}

__device__ __forceinline__ unsigned long long fadd2(unsigned long long a,
                                                    unsigned long long b)
{
    unsigned long long d;
    asm("add.rn.f32x2 %0, %1, %2;" : "=l"(d) : "l"(a), "l"(b));
    return d;
}

__device__ __forceinline__ float hsum2(unsigned long long a)
{
    float2 f;
    memcpy(&f, &a, 8);
    return f.x + f.y;
}

__device__ __forceinline__ float tanh_fast(float x)
{
    float y;
    asm("tanh.approx.f32 %0, %1;" : "=f"(y) : "f"(x));
    return y;
}

// ---------------------------------------------------------------------------
// Kernel 2: fused 2-layer RNN scan + head.
//
// Grid: 128 CTAs x 128 threads; CTA owns 2 batches (group g = tid>>6, 64
// threads, warps {2g, 2g+1}, independent named barrier per group).
// Thread u owns hidden unit u for both layers; 96 weight f32x2 regs.
//
// Retimed pipeline: phase p computes  h0[p]   (needs h0[p-1], post-bar)
//                               and  h1[p-2] (needs h0[p-2]  -> PRE-bar!
//                                             and h1[p-3],    post-bar)
// The L1a dot (Wih1[u] . h0[p-2]) reads data two barriers old, so it is
// issued BEFORE bar.sync, overlapping the previous phase's tanh/STS tail.
// h0: triple-buffered, h1: double-buffered.
// ---------------------------------------------------------------------------
__global__ __launch_bounds__(128, 1)
void rnn_scan_kernel(const int*   __restrict__ x,
                     const float* __restrict__ Whh0,
                     const float* __restrict__ Wih1,
                     const float* __restrict__ Whh1,
                     const float* __restrict__ bih1,
                     const float* __restrict__ bhh1,
                     const float* __restrict__ W1,
                     const float* __restrict__ b1,
                     const float* __restrict__ W2,
                     const float* __restrict__ b2,
                     float*       __restrict__ out)
{
    extern __shared__ float smem[];
    // layout: P0s[VOCAB*HID] | xs[2*TLEN] (int) | hbuf[2*(3*64 + 2*64)]
    float* P0s  = smem;
    int*   xs   = (int*)(smem + VOCAB * HID);
    float* hbuf = smem + VOCAB * HID + 2 * TLEN;

    const int tid  = threadIdx.x;
    const int g    = tid >> 6;       // batch group within CTA
    const int u    = tid & 63;       // hidden unit
    const int bidx = blockIdx.x * 2 + g;

    // ---- stage P0 table (float4), token rows; zero h buffers
    {
        const float4* srcp = (const float4*)g_P0;
        float4*       dstp = (float4*)P0s;
        for (int i = tid; i < (VOCAB * HID) / 4; i += 128) dstp[i] = srcp[i];
    }
    for (int i = tid; i < 2 * TLEN; i += 128)
        xs[i] = x[(blockIdx.x * 2 + (i >> 10)) * TLEN + (i & (TLEN - 1))];
    for (int i = tid; i < 2 * 320; i += 128) hbuf[i] = 0.0f;

    // ---- pack weights into 64-bit f32x2 registers (96 u64 = 192 floats)
    unsigned long long w0p[32], w1p[32], w2p[32];
    {
        const unsigned long long* a  = (const unsigned long long*)(Whh0 + u * HID);
        const unsigned long long* bq = (const unsigned long long*)(Wih1 + u * HID);
        const unsigned long long* c  = (const unsigned long long*)(Whh1 + u * HID);
        #pragma unroll
        for (int k = 0; k < 32; k++) { w0p[k] = a[k]; w1p[k] = bq[k]; w2p[k] = c[k]; }
    }
    const float c1 = bih1[u] + bhh1[u];

    __syncthreads();

    // per-group buffers: h0 x3, h1 x2 (64 floats each)
    float* base  = hbuf + g * 320;
    float* h0_w  = base;              // h0[p]   write target
    float* h0_r1 = base + 64;         // h0[p-1]
    float* h0_r2 = base + 128;        // h0[p-2]
    float* h1s0  = base + 192;        // h1 slot 0 (written phases p even)
    float* h1s1  = base + 256;        // h1 slot 1 (written phases p odd)
    const int barid = 1 + g;
    const int* xrow = xs + g * TLEN;

    // carried P0 value for phase 0
    float p0v = P0s[xrow[0] * HID + u];

    for (int p = 0; p <= TLEN + 1; p++) {
        // ================= PRE-BARRIER: L1a = Wih1[u] . h0[p-2] =============
        unsigned long long b0 = 0, b1a = 0, b2a = 0, b3a = 0;
        {
            const ulonglong2* hv2 = (const ulonglong2*)h0_r2;
            #pragma unroll
            for (int jj = 0; jj < 16; jj += 2) {
                ulonglong2 v0 = hv2[jj];
                ffma2(b0,  v0.x, w1p[2 * jj]);
                ffma2(b1a, v0.y, w1p[2 * jj + 1]);
                ulonglong2 v1 = hv2[jj + 1];
                ffma2(b2a, v1.x, w1p[2 * jj + 2]);
                ffma2(b3a, v1.y, w1p[2 * jj + 3]);
            }
        }

        asm volatile("bar.sync %0, 64;" :: "r"(barid) : "memory");

        // ================= POST-BARRIER =====================================
        const float* h1r = (p & 1) ? h1s0 : h1s1;   // h1[p-3]
        float*       h1w = (p & 1) ? h1s1 : h1s0;   // h1[p-2] target

        // L0: Whh0[u] . h0[p-1]   (4 accumulators, 8-deep chains)
        unsigned long long a0 = 0, a1 = 0, a2 = 0, a3 = 0;
        {
            const ulonglong2* hv2 = (const ulonglong2*)h0_r1;
            #pragma unroll
            for (int jj = 0; jj < 16; jj += 2) {
                ulonglong2 v0 = hv2[jj];
                ffma2(a0, v0.x, w0p[2 * jj]);
                ffma2(a1, v0.y, w0p[2 * jj + 1]);
                ulonglong2 v1 = hv2[jj + 1];
                ffma2(a2, v1.x, w0p[2 * jj + 2]);
                ffma2(a3, v1.y, w0p[2 * jj + 3]);
            }
        }

        // L1b: Whh1[u] . h1[p-3]  (4 accumulators)
        unsigned long long c0 = 0, c1b = 0, c2b = 0, c3b = 0;
        {
            const ulonglong2* gv2 = (const ulonglong2*)h1r;
            #pragma unroll
            for (int jj = 0; jj < 16; jj += 2) {
                ulonglong2 v0 = gv2[jj];
                ffma2(c0,  v0.x, w2p[2 * jj]);
                ffma2(c1b, v0.y, w2p[2 * jj + 1]);
                ulonglong2 v1 = gv2[jj + 1];
                ffma2(c2b, v1.x, w2p[2 * jj + 2]);
                ffma2(c3b, v1.y, w2p[2 * jj + 3]);
            }
        }

        // prefetch next phase's P0 value (58-cyc LDS chain, hidden here)
        const int tnext = (p + 1 < TLEN) ? (p + 1) : (TLEN - 1);
        const float p0n = P0s[xrow[tnext] * HID + u];

        // finalize h0[p]
        const float s0 = hsum2(fadd2(fadd2(a0, a1), fadd2(a2, a3)));
        if (p < TLEN) h0_w[u] = tanh_fast(s0 + p0v);

        // finalize h1[p-2]
        const float s1 = hsum2(fadd2(fadd2(b0, b1a), fadd2(b2a, b3a))) +
                         hsum2(fadd2(fadd2(c0, c1b), fadd2(c2b, c3b)));
        if (p >= 2) h1w[u] = tanh_fast(s1 + c1);

        p0v = p0n;

        // rotate h0 buffers: w -> r1 -> r2 -> w
        float* t = h0_r2; h0_r2 = h0_r1; h0_r1 = h0_w; h0_w = t;
    }

    asm volatile("bar.sync %0, 64;" :: "r"(barid) : "memory");

    // final h1[T-1] written at phase T+1 (odd for T=1024) -> slot 1
    const float* h1f = base + 256;

    // ---- head: y = relu(h1f @ W1^T + b1) @ W2^T + b2  (first warp of group)
    if (u < 32) {
        float acc = b1[u];
        #pragma unroll
        for (int k = 0; k < HID; k++)
            acc += W1[u * HID + k] * h1f[k];
        acc = fmaxf(acc, 0.0f);
        float s = acc * W2[u];
        #pragma unroll
        for (int off = 16; off; off >>= 1)
            s += __shfl_down_sync(0xffffffffu, s, off);
        if (u == 0) out[bidx] = s + b2[0];
    }
}

// ---------------------------------------------------------------------------
extern "C" void kernel_launch(void* const* d_in, const int* in_sizes, int n_in,
                              void* d_out, int out_size)
{
    const int*   x    = (const int*)  d_in[0];
    const float* emb  = (const float*)d_in[1];
    const float* Wih0 = (const float*)d_in[2];
    const float* Whh0 = (const float*)d_in[3];
    const float* bih0 = (const float*)d_in[4];
    const float* bhh0 = (const float*)d_in[5];
    const float* Wih1 = (const float*)d_in[6];
    const float* Whh1 = (const float*)d_in[7];
    const float* bih1 = (const float*)d_in[8];
    const float* bhh1 = (const float*)d_in[9];
    const float* W1   = (const float*)d_in[10];
    const float* b1   = (const float*)d_in[11];
    const float* W2   = (const float*)d_in[12];
    const float* b2   = (const float*)d_in[13];
    float* out = (float*)d_out;

    precompute_P0<<<VOCAB, 64>>>(emb, Wih0, bih0, bhh0);

    const int smem_bytes = (VOCAB * HID + 2 * TLEN + 2 * 320) * 4;  // 141,824 B
    cudaFuncSetAttribute(rnn_scan_kernel,
                         cudaFuncAttributeMaxDynamicSharedMemorySize, smem_bytes);
    rnn_scan_kernel<<<BATCH / 2, 128, smem_bytes>>>(
        x, Whh0, Wih1, Whh1, bih1, bhh1, W1, b1, W2, b2, out);
}